// round 9
// baseline (speedup 1.0000x reference)
#include <cuda_runtime.h>
#include <cuda_bf16.h>
#include <cstdint>

#define N_NODES 100000
#define E_MAX   1700000
#define SCAN_B  256

// ---------------- scratch (device globals; no allocation allowed) ----------
__device__ __nv_bfloat16 g_P1[N_NODES * 32];   // bf16 projected features (gathered)
__device__ __nv_bfloat16 g_P2[N_NODES * 32];
__device__ float g_R1[N_NODES * 32];
__device__ float g_H [N_NODES * 32];
__device__ float g_R2[N_NODES * 32];
__device__ int   g_cnt[N_NODES];
__device__ int   g_rowptr[N_NODES + 1];
__device__ int   g_col[E_MAX];
__device__ int   g_bsums[512];
__device__ int   g_is64;

// ---------------- zero cnt + edge-index dtype detection ---------------------
__global__ void zero_and_detect(int* __restrict__ cnt, const int* __restrict__ ei) {
    cudaGridDependencySynchronize();
    int i = blockIdx.x * blockDim.x + threadIdx.x;
    if (i < N_NODES) cnt[i] = 0;
    if (i == 0) {
        int allzero = 1;
        #pragma unroll
        for (int j = 1; j < 64; j += 2)
            if (ei[j] != 0) { allzero = 0; break; }
        g_is64 = allzero;
    }
}

__device__ __forceinline__ int load_idx(const void* ei, long long i) {
    return g_is64 ? (int)((const long long*)ei)[i] : ((const int*)ei)[i];
}

// ---------------- CSR build --------------------------------------------------
__global__ void count_edges(const void* __restrict__ ei, int E,
                            int* __restrict__ cnt) {
    cudaGridDependencySynchronize();
    int e = blockIdx.x * blockDim.x + threadIdx.x;
    if (e >= E) return;
    atomicAdd(cnt + load_idx(ei, (long long)E + e), 1);
}

__global__ void scan_blocks(const int* __restrict__ cnt,
                            int* __restrict__ rowptr,
                            int* __restrict__ bsums, int n) {
    cudaGridDependencySynchronize();
    __shared__ int wsum[8];
    int tid  = threadIdx.x;
    int wid  = tid >> 5;
    int lane = tid & 31;
    int i = blockIdx.x * SCAN_B + tid;
    int v = (i < n) ? cnt[i] : 0;

    int incl = v;
    #pragma unroll
    for (int o = 1; o < 32; o <<= 1) {
        int t = __shfl_up_sync(0xffffffffu, incl, o);
        if (lane >= o) incl += t;
    }
    if (lane == 31) wsum[wid] = incl;
    __syncthreads();
    if (wid == 0 && lane < 8) {
        int s = wsum[lane];
        int si = s;
        #pragma unroll
        for (int o = 1; o < 8; o <<= 1) {
            int t = __shfl_up_sync(0xffu, si, o);
            if (lane >= o) si += t;
        }
        wsum[lane] = si - s;
    }
    __syncthreads();
    incl += wsum[wid];
    if (i < n) rowptr[i] = incl - v;
    if (tid == SCAN_B - 1) bsums[blockIdx.x] = incl;
}

__global__ void add_offsets(int* __restrict__ rowptr,
                            const int* __restrict__ bsums, int n, int E) {
    cudaGridDependencySynchronize();
    __shared__ int carry;
    int b = blockIdx.x;
    if (threadIdx.x < 32) {
        int sum = 0;
        for (int j = (int)threadIdx.x; j < b; j += 32) sum += bsums[j];
        #pragma unroll
        for (int o = 16; o; o >>= 1) sum += __shfl_xor_sync(0xffffffffu, sum, o);
        if (threadIdx.x == 0) carry = sum;
    }
    __syncthreads();
    int i = b * SCAN_B + threadIdx.x;
    if (i < n) rowptr[i] += carry;
    if (i == 0) rowptr[n] = E;
}

__global__ void fill_csr(const void* __restrict__ ei, int E,
                         const int* __restrict__ rowptr,
                         int* __restrict__ cur, int* __restrict__ col) {
    cudaGridDependencySynchronize();
    int e = blockIdx.x * blockDim.x + threadIdx.x;
    if (e >= E) return;
    int s = load_idx(ei, e);
    int d = load_idx(ei, (long long)E + e);
    col[rowptr[d] + atomicSub(cur + d, 1) - 1] = s;
}

// ---------------- tf32 tensor-core dual GEMM: A[M,K] @ [Wl|Wr] --------------
// P written as bf16 (gathered later), R as fp32 (read once, coalesced)
__device__ __forceinline__ uint32_t f2tf32(float f) {
    uint32_t u;
    asm("cvt.rna.tf32.f32 %0, %1;" : "=r"(u) : "f"(f));
    return u;
}

#define LDA_T 20
#define LDW_T 68

template<int K>
__global__ __launch_bounds__(256, 2)
void gemm_tf32(const float* __restrict__ A,
               const float* __restrict__ Wl,
               const float* __restrict__ Wr,
               __nv_bfloat16* __restrict__ P,
               float* __restrict__ R, int M)
{
    cudaGridDependencySynchronize();
    __shared__ float As[128 * LDA_T];
    __shared__ float Ws[K * LDW_T];

    const int tid  = threadIdx.x;
    const int wid  = tid >> 5;
    const int lane = tid & 31;
    const int row0 = blockIdx.x * 128;

    #pragma unroll
    for (int idx = tid; idx < K * 16; idx += 256) {
        int k  = idx >> 4;
        int j4 = (idx & 15) * 4;
        float4 v = (j4 < 32) ? *(const float4*)(Wl + k * 32 + j4)
                             : *(const float4*)(Wr + k * 32 + (j4 - 32));
        float4 o;
        o.x = __uint_as_float(f2tf32(v.x));
        o.y = __uint_as_float(f2tf32(v.y));
        o.z = __uint_as_float(f2tf32(v.z));
        o.w = __uint_as_float(f2tf32(v.w));
        *(float4*)(Ws + k * LDW_T + j4) = o;
    }

    float acc[8][4] = {};
    const int gr = lane >> 2;
    const int gt = lane & 3;

    for (int kc = 0; kc < K; kc += 16) {
        #pragma unroll
        for (int idx = tid; idx < 128 * 4; idx += 256) {
            int r  = idx >> 2;
            int c4 = (idx & 3) * 4;
            float4 v = make_float4(0.f, 0.f, 0.f, 0.f);
            if (row0 + r < M) v = *(const float4*)(A + (size_t)(row0 + r) * K + kc + c4);
            float4 o;
            o.x = __uint_as_float(f2tf32(v.x));
            o.y = __uint_as_float(f2tf32(v.y));
            o.z = __uint_as_float(f2tf32(v.z));
            o.w = __uint_as_float(f2tf32(v.w));
            *(float4*)(As + r * LDA_T + c4) = o;
        }
        __syncthreads();

        #pragma unroll
        for (int kk = 0; kk < 2; kk++) {
            const uint32_t* asb = (const uint32_t*)As;
            const uint32_t* wsb = (const uint32_t*)Ws;
            int ra = wid * 16 + gr;
            int ca = kk * 8 + gt;
            uint32_t a0 = asb[ra * LDA_T + ca];
            uint32_t a1 = asb[(ra + 8) * LDA_T + ca];
            uint32_t a2 = asb[ra * LDA_T + ca + 4];
            uint32_t a3 = asb[(ra + 8) * LDA_T + ca + 4];
            int kb = kc + kk * 8;
            #pragma unroll
            for (int nt = 0; nt < 8; nt++) {
                uint32_t b0 = wsb[(kb + gt) * LDW_T + nt * 8 + gr];
                uint32_t b1 = wsb[(kb + gt + 4) * LDW_T + nt * 8 + gr];
                asm volatile(
                    "mma.sync.aligned.m16n8k8.row.col.f32.tf32.tf32.f32 "
                    "{%0,%1,%2,%3}, {%4,%5,%6,%7}, {%8,%9}, {%0,%1,%2,%3};"
                    : "+f"(acc[nt][0]), "+f"(acc[nt][1]),
                      "+f"(acc[nt][2]), "+f"(acc[nt][3])
                    : "r"(a0), "r"(a1), "r"(a2), "r"(a3), "r"(b0), "r"(b1));
            }
        }
        __syncthreads();
    }

    int r = row0 + wid * 16 + gr;
    #pragma unroll
    for (int nt = 0; nt < 8; nt++) {
        int colg = nt * 8 + gt * 2;
        if (nt < 4) {   // P: bf16x2 stores
            if (r < M)
                *((__nv_bfloat162*)(P + (size_t)r * 32) + (colg >> 1)) =
                    __floats2bfloat162_rn(acc[nt][0], acc[nt][1]);
            if (r + 8 < M)
                *((__nv_bfloat162*)(P + (size_t)(r + 8) * 32) + (colg >> 1)) =
                    __floats2bfloat162_rn(acc[nt][2], acc[nt][3]);
        } else {        // R: fp32 stores
            int c = colg - 32;
            if (r < M)
                *(float2*)(R + (size_t)r * 32 + c) = make_float2(acc[nt][0], acc[nt][1]);
            if (r + 8 < M)
                *(float2*)(R + (size_t)(r + 8) * 32 + c) = make_float2(acc[nt][2], acc[nt][3]);
        }
    }
}

// ---------------- fused bf16 CSR aggregation + mean + bias + relu -----------
// one warp per node; lane = (q, c): q = edge slot 0..7, c = 16B chunk 0..3
// each 16B chunk = 8 bf16 columns; fp32 accumulation.
__device__ __forceinline__ void acc_bf16x8(float2* a, uint4 v) {
    float2 f0 = __bfloat1622float2(*(__nv_bfloat162*)&v.x);
    float2 f1 = __bfloat1622float2(*(__nv_bfloat162*)&v.y);
    float2 f2 = __bfloat1622float2(*(__nv_bfloat162*)&v.z);
    float2 f3 = __bfloat1622float2(*(__nv_bfloat162*)&v.w);
    a[0].x += f0.x; a[0].y += f0.y;
    a[1].x += f1.x; a[1].y += f1.y;
    a[2].x += f2.x; a[2].y += f2.y;
    a[3].x += f3.x; a[3].y += f3.y;
}

__global__ __launch_bounds__(256)
void agg_bf16(const int* __restrict__ rowptr,
              const int* __restrict__ col,
              const __nv_bfloat16* __restrict__ P,
              const float* __restrict__ R,
              const float* __restrict__ b,
              float* __restrict__ out)
{
    cudaGridDependencySynchronize();
    int warp = (blockIdx.x * blockDim.x + threadIdx.x) >> 5;
    int lane = threadIdx.x & 31;
    if (warp >= N_NODES) return;

    const int q = lane >> 2;   // edge slot within batch of 8
    const int c = lane & 3;    // 16-byte chunk (8 bf16 cols)

    int beg = rowptr[warp];
    int end = rowptr[warp + 1];

    float2 a[4] = {{0.f,0.f},{0.f,0.f},{0.f,0.f},{0.f,0.f}};
    float2 a2[4] = {{0.f,0.f},{0.f,0.f},{0.f,0.f},{0.f,0.f}};

    int i = beg;
    for (; i + 16 <= end; i += 16) {
        int s0 = __ldg(col + i + q);
        int s1 = __ldg(col + i + 8 + q);
        uint4 v0 = __ldg((const uint4*)(P + (size_t)s0 * 32) + c);
        uint4 v1 = __ldg((const uint4*)(P + (size_t)s1 * 32) + c);
        acc_bf16x8(a,  v0);
        acc_bf16x8(a2, v1);
    }
    if (i + 8 <= end) {
        int s0 = __ldg(col + i + q);
        uint4 v0 = __ldg((const uint4*)(P + (size_t)s0 * 32) + c);
        acc_bf16x8(a, v0);
        i += 8;
    }
    if (i + q < end) {
        int s0 = __ldg(col + i + q);
        uint4 v0 = __ldg((const uint4*)(P + (size_t)s0 * 32) + c);
        acc_bf16x8(a2, v0);
    }
    #pragma unroll
    for (int j = 0; j < 4; j++) { a[j].x += a2[j].x; a[j].y += a2[j].y; }

    // reduce over the 8 edge-slot groups (xor 4, 8, 16)
    #pragma unroll
    for (int o = 4; o <= 16; o <<= 1) {
        #pragma unroll
        for (int j = 0; j < 4; j++) {
            a[j].x += __shfl_xor_sync(0xffffffffu, a[j].x, o);
            a[j].y += __shfl_xor_sync(0xffffffffu, a[j].y, o);
        }
    }

    if (q == 0) {
        // lane c owns cols c*8 .. c*8+7
        float invd = 1.0f / fmaxf((float)(end - beg), 1.0f);
        const float* rb = R + (size_t)warp * 32 + c * 8;
        float4 r0 = __ldg((const float4*)rb);
        float4 r1 = __ldg((const float4*)rb + 1);
        float4 b0 = __ldg((const float4*)(b + c * 8));
        float4 b1 = __ldg((const float4*)(b + c * 8) + 1);
        float4 o0, o1;
        o0.x = fmaxf(fmaf(a[0].x, invd, b0.x) + r0.x, 0.f);
        o0.y = fmaxf(fmaf(a[0].y, invd, b0.y) + r0.y, 0.f);
        o0.z = fmaxf(fmaf(a[1].x, invd, b0.z) + r0.z, 0.f);
        o0.w = fmaxf(fmaf(a[1].y, invd, b0.w) + r0.w, 0.f);
        o1.x = fmaxf(fmaf(a[2].x, invd, b1.x) + r1.x, 0.f);
        o1.y = fmaxf(fmaf(a[2].y, invd, b1.y) + r1.y, 0.f);
        o1.z = fmaxf(fmaf(a[3].x, invd, b1.z) + r1.z, 0.f);
        o1.w = fmaxf(fmaf(a[3].y, invd, b1.w) + r1.w, 0.f);
        float* ob = out + (size_t)warp * 32 + c * 8;
        *(float4*)ob       = o0;
        *((float4*)ob + 1) = o1;
    }
}

// ---------------- PDL launch helper -----------------------------------------
template<typename F, typename... Args>
static inline void launch_pdl(F* k, dim3 grid, dim3 block, Args... args) {
    cudaLaunchConfig_t cfg = {};
    cfg.gridDim  = grid;
    cfg.blockDim = block;
    cfg.dynamicSmemBytes = 0;
    cfg.stream = 0;
    cudaLaunchAttribute at[1];
    at[0].id = cudaLaunchAttributeProgrammaticStreamSerialization;
    at[0].val.programmaticStreamSerializationAllowed = 1;
    cfg.attrs = at;
    cfg.numAttrs = 1;
    cudaLaunchKernelEx(&cfg, k, args...);
}

// ---------------- launcher --------------------------------------------------
extern "C" void kernel_launch(void* const* d_in, const int* in_sizes, int n_in,
                              void* d_out, int out_size)
{
    const float* x   = (const float*)d_in[0];
    const void*  ei  = d_in[1];
    const float* W1l = (const float*)d_in[2];
    const float* b1l = (const float*)d_in[3];
    const float* W1r = (const float*)d_in[4];
    const float* W2l = (const float*)d_in[5];
    const float* b2l = (const float*)d_in[6];
    const float* W2r = (const float*)d_in[7];
    float* out = (float*)d_out;

    const int E = in_sizes[1] / 2;
    const int M = N_NODES;

    __nv_bfloat16 *P1, *P2;
    float *R1, *H, *R2;
    int *cnt, *rowptr, *colA, *bsums;
    cudaGetSymbolAddress((void**)&P1,     g_P1);
    cudaGetSymbolAddress((void**)&P2,     g_P2);
    cudaGetSymbolAddress((void**)&R1,     g_R1);
    cudaGetSymbolAddress((void**)&H,      g_H);
    cudaGetSymbolAddress((void**)&R2,     g_R2);
    cudaGetSymbolAddress((void**)&cnt,    g_cnt);
    cudaGetSymbolAddress((void**)&rowptr, g_rowptr);
    cudaGetSymbolAddress((void**)&colA,   g_col);
    cudaGetSymbolAddress((void**)&bsums,  g_bsums);

    static cudaStream_t s_side = [](){
        cudaStream_t s; cudaStreamCreateWithFlags(&s, cudaStreamNonBlocking); return s;
    }();
    static cudaEvent_t s_evFork = [](){
        cudaEvent_t e; cudaEventCreateWithFlags(&e, cudaEventDisableTiming); return e;
    }();
    static cudaEvent_t s_evJoin = [](){
        cudaEvent_t e; cudaEventCreateWithFlags(&e, cudaEventDisableTiming); return e;
    }();

    const int edge_blocks   = (E + 255) / 256;
    const int scan_blocks_n = (M + SCAN_B - 1) / SCAN_B;
    const int agg_blocks    = (M * 32 + 255) / 256;

    // fork: gemm1 runs on side stream concurrently with CSR build
    cudaEventRecord(s_evFork, 0);
    cudaStreamWaitEvent(s_side, s_evFork, 0);
    gemm_tf32<128><<<(M + 127) / 128, 256, 0, s_side>>>(x, W1l, W1r, P1, R1, M);
    cudaEventRecord(s_evJoin, s_side);

    launch_pdl(zero_and_detect, dim3((M + 1023) / 1024), dim3(1024), cnt, (const int*)ei);
    launch_pdl(count_edges, dim3(edge_blocks), dim3(256), ei, E, cnt);
    launch_pdl(scan_blocks, dim3(scan_blocks_n), dim3(SCAN_B), (const int*)cnt, rowptr, bsums, M);
    launch_pdl(add_offsets, dim3(scan_blocks_n), dim3(SCAN_B), rowptr, (const int*)bsums, M, E);
    launch_pdl(fill_csr, dim3(edge_blocks), dim3(256), ei, E, (const int*)rowptr, cnt, colA);

    cudaStreamWaitEvent(0, s_evJoin, 0);

    launch_pdl(agg_bf16, dim3(agg_blocks), dim3(256),
               (const int*)rowptr, (const int*)colA,
               (const __nv_bfloat16*)P1, (const float*)R1, b1l, H);
    launch_pdl(gemm_tf32<32>, dim3((M + 127) / 128), dim3(256),
               (const float*)H, W2l, W2r, P2, R2, M);
    launch_pdl(agg_bf16, dim3(agg_blocks), dim3(256),
               (const int*)rowptr, (const int*)colA,
               (const __nv_bfloat16*)P2, (const float*)R2, b2l, out);
}